// round 15
// baseline (speedup 1.0000x reference)
#include <cuda_runtime.h>
#include <cuda_fp16.h>
#include <cstdint>

#define M_DIM 16384
#define N_DIM 8192
#define K_DIM 64

#define THREADS 256            // 8 warps; each warp covers 16 m
#define M_CTA 128
#define NSPLIT 8
#define NRANGE (N_DIM / NSPLIT)      // 1024
#define NSTEPS (NRANGE / 16)         // 64 per CTA
#define NTILES (M_DIM / M_CTA)       // 128

// fp16 B fragments: u32 idx = ((s*4 + ktp)*32 + lane)*4 + j
#define BFRAG_U32 (512 * 4 * 32 * 4)    // 1MB
#define NPAIRS (N_DIM / 2)

typedef unsigned long long ull;

// ---- device scratch ----
__device__ uint32_t g_Bfrag[BFRAG_U32];
// per n-pair: {bx0,bx1, by0,by1, bz0,bz1, c0,c1}; b=-2e^2 x, c=e^2|x|^2+1
__device__ float g_Xpk[NPAIRS * 8];
__device__ float g_part[NSPLIT][M_DIM * K_DIM];  // partials, 32MB

// ---- helpers ----
__device__ __forceinline__ ull ffma2(ull a, ull b, ull c) {
    ull d; asm("fma.rn.f32x2 %0, %1, %2, %3;" : "=l"(d) : "l"(a), "l"(b), "l"(c)); return d;
}
__device__ __forceinline__ ull fadd2(ull a, ull b) {
    ull d; asm("add.rn.f32x2 %0, %1, %2;" : "=l"(d) : "l"(a), "l"(b)); return d;
}
__device__ __forceinline__ ull splat2(float v) {
    ull d; asm("mov.b64 %0, {%1, %1};" : "=l"(d) : "f"(v)); return d;
}
__device__ __forceinline__ void unpack2(ull p, float& lo, float& hi) {
    asm("mov.b64 {%0, %1}, %2;" : "=f"(lo), "=f"(hi) : "l"(p));
}
__device__ __forceinline__ float fast_sqrt(float x) {
    float r; asm("sqrt.approx.f32 %0, %1;" : "=f"(r) : "f"(x)); return r;
}
__device__ __forceinline__ void mma_fp16(float* d, uint32_t a0, uint32_t a1,
                                         uint32_t a2, uint32_t a3,
                                         uint32_t b0, uint32_t b1) {
    asm volatile(
        "mma.sync.aligned.m16n8k16.row.col.f32.f16.f16.f32 "
        "{%0,%1,%2,%3}, {%4,%5,%6,%7}, {%8,%9}, {%0,%1,%2,%3};"
        : "+f"(d[0]), "+f"(d[1]), "+f"(d[2]), "+f"(d[3])
        : "r"(a0), "r"(a1), "r"(a2), "r"(a3), "r"(b0), "r"(b1));
}

// ---- merged prep: X pair vectors + W fp16 fragment shredding ----
__global__ __launch_bounds__(256)
void prep_all(const float* __restrict__ W, const float* __restrict__ X,
              const float* __restrict__ epsp) {
    int idx = blockIdx.x * 256 + threadIdx.x;

    if (idx < NPAIRS) {   // adjacent pair p -> n = 2p, 2p+1
        float e = *epsp;
        float e2 = e * e;
        const float* x0 = X + (size_t)(2 * idx) * 3;
        float a0 = x0[0], a1 = x0[1], a2 = x0[2];
        float b0 = x0[3], b1 = x0[4], b2 = x0[5];
        float* o = g_Xpk + (size_t)idx * 8;
        o[0] = -2.0f * e2 * a0; o[1] = -2.0f * e2 * b0;
        o[2] = -2.0f * e2 * a1; o[3] = -2.0f * e2 * b1;
        o[4] = -2.0f * e2 * a2; o[5] = -2.0f * e2 * b2;
        o[6] = fmaf(e2, a0 * a0 + a1 * a1 + a2 * a2, 1.0f);
        o[7] = fmaf(e2, b0 * b0 + b1 * b1 + b2 * b2, 1.0f);
    }

    // B fragment shred (idx covers BFRAG_U32)
    {
        int j   = idx & 3;
        int t   = (idx >> 2) & 31;
        int ktp = (idx >> 7) & 3;
        int s   = idx >> 9;

        int kt = ktp * 2 + (j >> 1);
        int km = (t & 3) * 2 + (j & 1) * 8;   // contraction n within step
        int nm = t >> 2;                      // output k within tile
        int kout = kt * 8 + nm;
        int n = s * 16 + km;

        float w0 = W[(size_t)kout * N_DIM + n];
        float w1 = W[(size_t)kout * N_DIM + n + 1];
        uint32_t packed;
        asm("cvt.rn.f16x2.f32 %0, %1, %2;" : "=r"(packed) : "f"(w1), "f"(w0));
        g_Bfrag[idx] = packed;
    }
}

// ---- main kernel: 8 warps x 16m, 3 CTAs/SM (24 warps) ----
__global__ __launch_bounds__(THREADS, 3)
void rbf_fp16(const float* __restrict__ Xp, const float* __restrict__ epsp) {
    const int tid  = threadIdx.x;
    const int warp = tid >> 5;           // 0..7
    const int lane = tid & 31;
    const int ns   = blockIdx.y;
    const int mwb  = blockIdx.x * M_CTA + warp * 16;   // warp m-base (16 rows)
    const int s0   = ns * NSTEPS;

    const float e = *epsp;
    const float e2 = e * e;

    // coords + Pm for this thread's 2 rows: u in {0,1}
    ull xs[2], ys[2], zs[2], pm[2];
#pragma unroll
    for (int u = 0; u < 2; u++) {
        int m = mwb + u * 8 + (lane >> 2);
        float px = Xp[m * 3 + 0], py = Xp[m * 3 + 1], pz = Xp[m * 3 + 2];
        xs[u] = splat2(px);
        ys[u] = splat2(py);
        zs[u] = splat2(pz);
        pm[u] = splat2(e2 * (px * px + py * py + pz * pz));
    }

    float acc[8][4];
#pragma unroll
    for (int k = 0; k < 8; k++)
#pragma unroll
        for (int j = 0; j < 4; j++) acc[k][j] = 0.0f;

    const float* xp = g_Xpk + ((size_t)s0 * 8 + (lane & 3)) * 8;
    const uint4* bf = reinterpret_cast<const uint4*>(g_Bfrag) + (size_t)s0 * 4 * 32 + lane;

    for (int s = 0; s < NSTEPS; s++) {
        // B fragments for this step (4 x LDG.128; identical across warps -> L1 hits)
        uint4 bfr0 = __ldg(bf + 0 * 32);
        uint4 bfr1 = __ldg(bf + 1 * 32);
        uint4 bfr2 = __ldg(bf + 2 * 32);
        uint4 bfr3 = __ldg(bf + 3 * 32);
        bf += 4 * 32;

        // pair vectors: p=0 at +0, p=1 at +32 floats; (bx,by) then (bz,c)
        ulonglong2 A0 = *reinterpret_cast<const ulonglong2*>(xp);
        ulonglong2 B0 = *reinterpret_cast<const ulonglong2*>(xp + 4);
        ulonglong2 A1 = *reinterpret_cast<const ulonglong2*>(xp + 32);
        ulonglong2 B1 = *reinterpret_cast<const ulonglong2*>(xp + 36);
        xp += 64;

        // phi -> fp16 A fragment (one 16x16 tile)
        uint32_t ah[4];
#pragma unroll
        for (int u = 0; u < 2; u++) {
#pragma unroll
            for (int p = 0; p < 2; p++) {
                ull base = fadd2(p ? B1.y : B0.y, pm[u]);
                ull tt = ffma2(xs[u], p ? A1.x : A0.x,
                         ffma2(ys[u], p ? A1.y : A0.y,
                         ffma2(zs[u], p ? B1.x : B0.x, base)));
                float t0, t1; unpack2(tt, t0, t1);
                float sq0 = fast_sqrt(t0), sq1 = fast_sqrt(t1);
                uint32_t hb;
                asm("cvt.rn.f16x2.f32 %0, %1, %2;" : "=r"(hb) : "f"(sq1), "f"(sq0));
                ah[u + 2 * p] = hb;
            }
        }

        // 8 MMAs per step
        mma_fp16(acc[0], ah[0], ah[1], ah[2], ah[3], bfr0.x, bfr0.y);
        mma_fp16(acc[1], ah[0], ah[1], ah[2], ah[3], bfr0.z, bfr0.w);
        mma_fp16(acc[2], ah[0], ah[1], ah[2], ah[3], bfr1.x, bfr1.y);
        mma_fp16(acc[3], ah[0], ah[1], ah[2], ah[3], bfr1.z, bfr1.w);
        mma_fp16(acc[4], ah[0], ah[1], ah[2], ah[3], bfr2.x, bfr2.y);
        mma_fp16(acc[5], ah[0], ah[1], ah[2], ah[3], bfr2.z, bfr2.w);
        mma_fp16(acc[6], ah[0], ah[1], ah[2], ah[3], bfr3.x, bfr3.y);
        mma_fp16(acc[7], ah[0], ah[1], ah[2], ah[3], bfr3.z, bfr3.w);
    }

    // epilogue: write partials
    float* part = g_part[ns];
    int rbase = mwb + (lane >> 2);
#pragma unroll
    for (int kt = 0; kt < 8; kt++) {
        int c = kt * 8 + (lane & 3) * 2;
        *reinterpret_cast<float2*>(&part[(size_t)rbase * K_DIM + c]) =
            make_float2(acc[kt][0], acc[kt][1]);
        *reinterpret_cast<float2*>(&part[(size_t)(rbase + 8) * K_DIM + c]) =
            make_float2(acc[kt][2], acc[kt][3]);
    }
}

// ---- reduce: 8 partials, one float4 per thread ----
__global__ __launch_bounds__(256)
void reduce_parts(float* __restrict__ out) {
    int i = blockIdx.x * 256 + threadIdx.x;
    float4 r = __ldg(reinterpret_cast<const float4*>(g_part[0]) + i);
#pragma unroll
    for (int p = 1; p < NSPLIT; p++) {
        float4 v = __ldg(reinterpret_cast<const float4*>(g_part[p]) + i);
        r.x += v.x; r.y += v.y; r.z += v.z; r.w += v.w;
    }
    reinterpret_cast<float4*>(out)[i] = r;
}

// ---- dummy: pads launch count so ncu (-s 5) lands on rbf_fp16 of call 2 ----
__global__ void dummy_noop() {}

extern "C" void kernel_launch(void* const* d_in, const int* in_sizes, int n_in,
                              void* d_out, int out_size) {
    const float* Xp  = (const float*)d_in[0];
    const float* X   = (const float*)d_in[1];
    const float* W   = (const float*)d_in[2];
    const float* eps = (const float*)d_in[3];
    float* out = (float*)d_out;

    prep_all<<<BFRAG_U32 / 256, 256>>>(W, X, eps);

    dim3 grid(NTILES, NSPLIT);   // 128 x 8 = 1024 CTAs, 256 thr
    rbf_fp16<<<grid, THREADS>>>(Xp, eps);

    reduce_parts<<<(M_DIM * K_DIM / 4) / 256, 256>>>(out);

    dummy_noop<<<1, 32>>>();
}

// round 16
// speedup vs baseline: 1.0561x; 1.0561x over previous
#include <cuda_runtime.h>
#include <cuda_fp16.h>
#include <cstdint>

#define M_DIM 16384
#define N_DIM 8192
#define K_DIM 64

#define THREADS 128            // 4 warps
#define M_CTA 128              // warp covers 32 m
#define NSPLIT 4
#define NRANGE (N_DIM / NSPLIT)      // 2048
#define NSTEPS (NRANGE / 16)         // 128 per CTA
#define NTILES (M_DIM / M_CTA)       // 128

// fp16 B fragments: u32 idx = ((s*4 + ktp)*32 + lane)*4 + j
#define BFRAG_U32 (512 * 4 * 32 * 4)    // 1MB
#define NPAIRS (N_DIM / 2)

typedef unsigned long long ull;

// ---- device scratch ----
__device__ uint32_t g_Bfrag[BFRAG_U32];
// per n-pair: {bx0,bx1, by0,by1, bz0,bz1, c0,c1}; b=-2e^2 x, c=e^2|x|^2+1
__device__ float g_Xpk[NPAIRS * 8];
__device__ float g_part[NSPLIT][M_DIM * K_DIM];  // partials, 16MB

// ---- helpers ----
__device__ __forceinline__ ull ffma2(ull a, ull b, ull c) {
    ull d; asm("fma.rn.f32x2 %0, %1, %2, %3;" : "=l"(d) : "l"(a), "l"(b), "l"(c)); return d;
}
__device__ __forceinline__ ull fadd2(ull a, ull b) {
    ull d; asm("add.rn.f32x2 %0, %1, %2;" : "=l"(d) : "l"(a), "l"(b)); return d;
}
__device__ __forceinline__ ull splat2(float v) {
    ull d; asm("mov.b64 %0, {%1, %1};" : "=l"(d) : "f"(v)); return d;
}
__device__ __forceinline__ void unpack2(ull p, float& lo, float& hi) {
    asm("mov.b64 {%0, %1}, %2;" : "=f"(lo), "=f"(hi) : "l"(p));
}
__device__ __forceinline__ float fast_sqrt(float x) {
    float r; asm("sqrt.approx.f32 %0, %1;" : "=f"(r) : "f"(x)); return r;
}
__device__ __forceinline__ uint32_t smem_u32(const void* p) {
    uint32_t a;
    asm("{ .reg .u64 t; cvta.to.shared.u64 t, %1; cvt.u32.u64 %0, t; }" : "=r"(a) : "l"(p));
    return a;
}
__device__ __forceinline__ void cp_async16(uint32_t smem_addr, const void* gmem) {
    asm volatile("cp.async.cg.shared.global [%0], [%1], 16;"
                 :: "r"(smem_addr), "l"(gmem) : "memory");
}
__device__ __forceinline__ void cp_async_commit() {
    asm volatile("cp.async.commit_group;" ::: "memory");
}
__device__ __forceinline__ void cp_async_wait0() {
    asm volatile("cp.async.wait_group 0;" ::: "memory");
}
__device__ __forceinline__ void mma_fp16(float* d, uint32_t a0, uint32_t a1,
                                         uint32_t a2, uint32_t a3,
                                         uint32_t b0, uint32_t b1) {
    asm volatile(
        "mma.sync.aligned.m16n8k16.row.col.f32.f16.f16.f32 "
        "{%0,%1,%2,%3}, {%4,%5,%6,%7}, {%8,%9}, {%0,%1,%2,%3};"
        : "+f"(d[0]), "+f"(d[1]), "+f"(d[2]), "+f"(d[3])
        : "r"(a0), "r"(a1), "r"(a2), "r"(a3), "r"(b0), "r"(b1));
}

// ---- merged prep: X pair vectors + W fp16 fragment shredding ----
__global__ __launch_bounds__(256)
void prep_all(const float* __restrict__ W, const float* __restrict__ X,
              const float* __restrict__ epsp) {
    int idx = blockIdx.x * 256 + threadIdx.x;

    if (idx < NPAIRS) {   // adjacent pair p -> n = 2p, 2p+1
        float e = *epsp;
        float e2 = e * e;
        const float* x0 = X + (size_t)(2 * idx) * 3;
        float a0 = x0[0], a1 = x0[1], a2 = x0[2];
        float b0 = x0[3], b1 = x0[4], b2 = x0[5];
        float* o = g_Xpk + (size_t)idx * 8;
        o[0] = -2.0f * e2 * a0; o[1] = -2.0f * e2 * b0;
        o[2] = -2.0f * e2 * a1; o[3] = -2.0f * e2 * b1;
        o[4] = -2.0f * e2 * a2; o[5] = -2.0f * e2 * b2;
        o[6] = fmaf(e2, a0 * a0 + a1 * a1 + a2 * a2, 1.0f);
        o[7] = fmaf(e2, b0 * b0 + b1 * b1 + b2 * b2, 1.0f);
    }

    // B fragment shred (idx covers BFRAG_U32)
    {
        int j   = idx & 3;
        int t   = (idx >> 2) & 31;
        int ktp = (idx >> 7) & 3;
        int s   = idx >> 9;

        int kt = ktp * 2 + (j >> 1);
        int km = (t & 3) * 2 + (j & 1) * 8;   // contraction n within step
        int nm = t >> 2;                      // output k within tile
        int kout = kt * 8 + nm;
        int n = s * 16 + km;

        float w0 = W[(size_t)kout * N_DIM + n];
        float w1 = W[(size_t)kout * N_DIM + n + 1];
        uint32_t packed;
        asm("cvt.rn.f16x2.f32 %0, %1, %2;" : "=r"(packed) : "f"(w1), "f"(w0));
        g_Bfrag[idx] = packed;
    }
}

// ---- main kernel: R11 structure + cp.async double-buffered B staging ----
__global__ __launch_bounds__(THREADS, 4)
void rbf_fp16(const float* __restrict__ Xp, const float* __restrict__ epsp) {
    __shared__ __align__(16) uint4 sB[2][128];   // [buf][ktp*32 + lane], 4KB

    const int tid  = threadIdx.x;
    const int warp = tid >> 5;
    const int lane = tid & 31;
    const int ns   = blockIdx.y;
    const int mwb  = blockIdx.x * M_CTA + warp * 32;   // warp m-base
    const int s0   = ns * NSTEPS;                      // first n-step

    const float e = *epsp;
    const float e2 = e * e;

    // raw Xp coords + Pm = e^2 |xp|^2 for this thread's 4 rows: ci = mtile*2 + u
    ull xs[4], ys[4], zs[4], pm[4];
#pragma unroll
    for (int i = 0; i < 4; i++) {
        int mtile = i >> 1, u = i & 1;
        int m = mwb + mtile * 16 + u * 8 + (lane >> 2);
        float px = Xp[m * 3 + 0], py = Xp[m * 3 + 1], pz = Xp[m * 3 + 2];
        xs[i] = splat2(px);
        ys[i] = splat2(py);
        zs[i] = splat2(pz);
        pm[i] = splat2(e2 * (px * px + py * py + pz * pz));
    }

    float acc[2][8][4];
#pragma unroll
    for (int t = 0; t < 2; t++)
#pragma unroll
        for (int k = 0; k < 8; k++)
#pragma unroll
            for (int j = 0; j < 4; j++) acc[t][k][j] = 0.0f;

    const float* xp = g_Xpk + ((size_t)s0 * 8 + (lane & 3)) * 8;

    // B staging: thread tid owns 16B chunk tid of each 2KB tile
    const uint4* bsrc = reinterpret_cast<const uint4*>(g_Bfrag) + (size_t)s0 * 4 * 32 + tid;
    const uint32_t sb0 = smem_u32(&sB[0][tid]);
    const uint32_t sb1 = smem_u32(&sB[1][tid]);

    // prologue: prefetch step 0 into buf 0
    cp_async16(sb0, bsrc);
    cp_async_commit();

    for (int s = 0; s < NSTEPS; s++) {
        const int buf = s & 1;

        cp_async_wait0();      // current buf tile landed
        __syncthreads();       // visible to all warps; prev buf fully consumed

        // prefetch next step into the other buffer (covered by this step's work)
        if (s + 1 < NSTEPS) {
            cp_async16(buf ? sb0 : sb1, bsrc + (size_t)(s + 1) * 4 * 32);
            cp_async_commit();
        }

        // B fragments from SMEM (4 x LDS.128, conflict-free)
        uint4 bfr0 = sB[buf][0 * 32 + lane];
        uint4 bfr1 = sB[buf][1 * 32 + lane];
        uint4 bfr2 = sB[buf][2 * 32 + lane];
        uint4 bfr3 = sB[buf][3 * 32 + lane];

        // pair vectors: p=0 at +0, p=1 at +32 floats; (bx,by) then (bz,c)
        ulonglong2 A0 = *reinterpret_cast<const ulonglong2*>(xp);
        ulonglong2 B0 = *reinterpret_cast<const ulonglong2*>(xp + 4);
        ulonglong2 A1 = *reinterpret_cast<const ulonglong2*>(xp + 32);
        ulonglong2 B1 = *reinterpret_cast<const ulonglong2*>(xp + 36);
        xp += 64;

        // ---- mtile 0: phi -> fragments, then MMAs ----
        uint32_t ah0[4], ah1[4];
#pragma unroll
        for (int u = 0; u < 2; u++) {
            int ci = u;  // mtile 0
#pragma unroll
            for (int p = 0; p < 2; p++) {
                ull base = fadd2(p ? B1.y : B0.y, pm[ci]);
                ull tt = ffma2(xs[ci], p ? A1.x : A0.x,
                         ffma2(ys[ci], p ? A1.y : A0.y,
                         ffma2(zs[ci], p ? B1.x : B0.x, base)));
                float t0, t1; unpack2(tt, t0, t1);
                float sq0 = fast_sqrt(t0), sq1 = fast_sqrt(t1);
                uint32_t hb;
                asm("cvt.rn.f16x2.f32 %0, %1, %2;" : "=r"(hb) : "f"(sq1), "f"(sq0));
                ah0[u + 2 * p] = hb;
            }
        }
        mma_fp16(acc[0][0], ah0[0], ah0[1], ah0[2], ah0[3], bfr0.x, bfr0.y);
        mma_fp16(acc[0][1], ah0[0], ah0[1], ah0[2], ah0[3], bfr0.z, bfr0.w);
        mma_fp16(acc[0][2], ah0[0], ah0[1], ah0[2], ah0[3], bfr1.x, bfr1.y);
        mma_fp16(acc[0][3], ah0[0], ah0[1], ah0[2], ah0[3], bfr1.z, bfr1.w);
        mma_fp16(acc[0][4], ah0[0], ah0[1], ah0[2], ah0[3], bfr2.x, bfr2.y);
        mma_fp16(acc[0][5], ah0[0], ah0[1], ah0[2], ah0[3], bfr2.z, bfr2.w);
        mma_fp16(acc[0][6], ah0[0], ah0[1], ah0[2], ah0[3], bfr3.x, bfr3.y);
        mma_fp16(acc[0][7], ah0[0], ah0[1], ah0[2], ah0[3], bfr3.z, bfr3.w);

        // ---- mtile 1 ----
#pragma unroll
        for (int u = 0; u < 2; u++) {
            int ci = 2 + u;  // mtile 1
#pragma unroll
            for (int p = 0; p < 2; p++) {
                ull base = fadd2(p ? B1.y : B0.y, pm[ci]);
                ull tt = ffma2(xs[ci], p ? A1.x : A0.x,
                         ffma2(ys[ci], p ? A1.y : A0.y,
                         ffma2(zs[ci], p ? B1.x : B0.x, base)));
                float t0, t1; unpack2(tt, t0, t1);
                float sq0 = fast_sqrt(t0), sq1 = fast_sqrt(t1);
                uint32_t hb;
                asm("cvt.rn.f16x2.f32 %0, %1, %2;" : "=r"(hb) : "f"(sq1), "f"(sq0));
                ah1[u + 2 * p] = hb;
            }
        }
        mma_fp16(acc[1][0], ah1[0], ah1[1], ah1[2], ah1[3], bfr0.x, bfr0.y);
        mma_fp16(acc[1][1], ah1[0], ah1[1], ah1[2], ah1[3], bfr0.z, bfr0.w);
        mma_fp16(acc[1][2], ah1[0], ah1[1], ah1[2], ah1[3], bfr1.x, bfr1.y);
        mma_fp16(acc[1][3], ah1[0], ah1[1], ah1[2], ah1[3], bfr1.z, bfr1.w);
        mma_fp16(acc[1][4], ah1[0], ah1[1], ah1[2], ah1[3], bfr2.x, bfr2.y);
        mma_fp16(acc[1][5], ah1[0], ah1[1], ah1[2], ah1[3], bfr2.z, bfr2.w);
        mma_fp16(acc[1][6], ah1[0], ah1[1], ah1[2], ah1[3], bfr3.x, bfr3.y);
        mma_fp16(acc[1][7], ah1[0], ah1[1], ah1[2], ah1[3], bfr3.z, bfr3.w);
    }

    // epilogue: write partials
    float* part = g_part[ns];
#pragma unroll
    for (int mtile = 0; mtile < 2; mtile++) {
        int rbase = mwb + mtile * 16 + (lane >> 2);
#pragma unroll
        for (int kt = 0; kt < 8; kt++) {
            int c = kt * 8 + (lane & 3) * 2;
            *reinterpret_cast<float2*>(&part[(size_t)rbase * K_DIM + c]) =
                make_float2(acc[mtile][kt][0], acc[mtile][kt][1]);
            *reinterpret_cast<float2*>(&part[(size_t)(rbase + 8) * K_DIM + c]) =
                make_float2(acc[mtile][kt][2], acc[mtile][kt][3]);
        }
    }
}

// ---- reduce ----
__global__ __launch_bounds__(256)
void reduce_parts(float* __restrict__ out) {
    int i = blockIdx.x * 256 + threadIdx.x;
    float4 a = __ldg(reinterpret_cast<const float4*>(g_part[0]) + i);
    float4 b = __ldg(reinterpret_cast<const float4*>(g_part[1]) + i);
    float4 c = __ldg(reinterpret_cast<const float4*>(g_part[2]) + i);
    float4 d = __ldg(reinterpret_cast<const float4*>(g_part[3]) + i);
    float4 r;
    r.x = (a.x + b.x) + (c.x + d.x);
    r.y = (a.y + b.y) + (c.y + d.y);
    r.z = (a.z + b.z) + (c.z + d.z);
    r.w = (a.w + b.w) + (c.w + d.w);
    reinterpret_cast<float4*>(out)[i] = r;
}

// ---- dummy: pads launch count so ncu (-s 5) lands on rbf_fp16 of call 2 ----
__global__ void dummy_noop() {}

extern "C" void kernel_launch(void* const* d_in, const int* in_sizes, int n_in,
                              void* d_out, int out_size) {
    const float* Xp  = (const float*)d_in[0];
    const float* X   = (const float*)d_in[1];
    const float* W   = (const float*)d_in[2];
    const float* eps = (const float*)d_in[3];
    float* out = (float*)d_out;

    prep_all<<<BFRAG_U32 / 256, 256>>>(W, X, eps);

    dim3 grid(NTILES, NSPLIT);   // 128 x 4 = 512 CTAs
    rbf_fp16<<<grid, THREADS>>>(Xp, eps);

    reduce_parts<<<(M_DIM * K_DIM / 4) / 256, 256>>>(out);

    dummy_noop<<<1, 32>>>();
}

// round 17
// speedup vs baseline: 1.1510x; 1.0899x over previous
#include <cuda_runtime.h>
#include <cuda_fp16.h>
#include <cstdint>

#define M_DIM 16384
#define N_DIM 8192
#define K_DIM 64

#define THREADS 128            // 4 warps
#define M_CTA 128              // warp covers 32 m
#define NSPLIT 8
#define NRANGE (N_DIM / NSPLIT)      // 1024
#define NSTEPS (NRANGE / 16)         // 64 per CTA

// fp16 B fragments: u32 idx = ((s*4 + ktp)*32 + lane)*4 + j
#define BFRAG_U32 (512 * 4 * 32 * 4)    // 1MB
#define NPAIRS (N_DIM / 2)

typedef unsigned long long ull;

// ---- device scratch ----
__device__ uint32_t g_Bfrag[BFRAG_U32];
// per n-pair: {bx0,bx1, by0,by1, bz0,bz1, c0,c1}; b=-2e^2 x, c=e^2|x|^2+1
__device__ float g_Xpk[NPAIRS * 8];
__device__ float g_part[NSPLIT][M_DIM * K_DIM];  // partials, 32MB (L2-resident)

// ---- helpers ----
__device__ __forceinline__ ull ffma2(ull a, ull b, ull c) {
    ull d; asm("fma.rn.f32x2 %0, %1, %2, %3;" : "=l"(d) : "l"(a), "l"(b), "l"(c)); return d;
}
__device__ __forceinline__ ull fadd2(ull a, ull b) {
    ull d; asm("add.rn.f32x2 %0, %1, %2;" : "=l"(d) : "l"(a), "l"(b)); return d;
}
__device__ __forceinline__ ull splat2(float v) {
    ull d; asm("mov.b64 %0, {%1, %1};" : "=l"(d) : "f"(v)); return d;
}
__device__ __forceinline__ void unpack2(ull p, float& lo, float& hi) {
    asm("mov.b64 {%0, %1}, %2;" : "=f"(lo), "=f"(hi) : "l"(p));
}
__device__ __forceinline__ float fast_sqrt(float x) {
    float r; asm("sqrt.approx.f32 %0, %1;" : "=f"(r) : "f"(x)); return r;
}
__device__ __forceinline__ void mma_fp16(float* d, uint32_t a0, uint32_t a1,
                                         uint32_t a2, uint32_t a3,
                                         uint32_t b0, uint32_t b1) {
    asm volatile(
        "mma.sync.aligned.m16n8k16.row.col.f32.f16.f16.f32 "
        "{%0,%1,%2,%3}, {%4,%5,%6,%7}, {%8,%9}, {%0,%1,%2,%3};"
        : "+f"(d[0]), "+f"(d[1]), "+f"(d[2]), "+f"(d[3])
        : "r"(a0), "r"(a1), "r"(a2), "r"(a3), "r"(b0), "r"(b1));
}

// ---- merged prep: X pair vectors + W fp16 fragment shredding ----
__global__ __launch_bounds__(256)
void prep_all(const float* __restrict__ W, const float* __restrict__ X,
              const float* __restrict__ epsp) {
    int idx = blockIdx.x * 256 + threadIdx.x;

    if (idx < NPAIRS) {   // adjacent pair p -> n = 2p, 2p+1
        float e = *epsp;
        float e2 = e * e;
        const float* x0 = X + (size_t)(2 * idx) * 3;
        float a0 = x0[0], a1 = x0[1], a2 = x0[2];
        float b0 = x0[3], b1 = x0[4], b2 = x0[5];
        float* o = g_Xpk + (size_t)idx * 8;
        o[0] = -2.0f * e2 * a0; o[1] = -2.0f * e2 * b0;
        o[2] = -2.0f * e2 * a1; o[3] = -2.0f * e2 * b1;
        o[4] = -2.0f * e2 * a2; o[5] = -2.0f * e2 * b2;
        o[6] = fmaf(e2, a0 * a0 + a1 * a1 + a2 * a2, 1.0f);
        o[7] = fmaf(e2, b0 * b0 + b1 * b1 + b2 * b2, 1.0f);
    }

    // B fragment shred (idx covers BFRAG_U32)
    {
        int j   = idx & 3;
        int t   = (idx >> 2) & 31;
        int ktp = (idx >> 7) & 3;
        int s   = idx >> 9;

        int kt = ktp * 2 + (j >> 1);
        int km = (t & 3) * 2 + (j & 1) * 8;   // contraction n within step
        int nm = t >> 2;                      // output k within tile
        int kout = kt * 8 + nm;
        int n = s * 16 + km;

        float w0 = W[(size_t)kout * N_DIM + n];
        float w1 = W[(size_t)kout * N_DIM + n + 1];
        uint32_t packed;
        asm("cvt.rn.f16x2.f32 %0, %1, %2;" : "=r"(packed) : "f"(w1), "f"(w0));
        g_Bfrag[idx] = packed;
    }
}

// ---- main kernel (R13 structure; unroll-2 isolated test, volatile MMAs kept) ----
__global__ __launch_bounds__(THREADS, 4)
void rbf_fp16(const float* __restrict__ Xp, const float* __restrict__ epsp) {
    const int tid  = threadIdx.x;
    const int warp = tid >> 5;
    const int lane = tid & 31;
    const int ns   = blockIdx.y;
    const int mwb  = blockIdx.x * M_CTA + warp * 32;   // warp m-base
    const int s0   = ns * NSTEPS;                      // first n-step

    const float e = *epsp;
    const float e2 = e * e;

    // raw Xp coords + Pm = e^2 |xp|^2 for this thread's 4 rows: ci = mtile*2 + u
    ull xs[4], ys[4], zs[4], pm[4];
#pragma unroll
    for (int i = 0; i < 4; i++) {
        int mtile = i >> 1, u = i & 1;
        int m = mwb + mtile * 16 + u * 8 + (lane >> 2);
        float px = Xp[m * 3 + 0], py = Xp[m * 3 + 1], pz = Xp[m * 3 + 2];
        xs[i] = splat2(px);
        ys[i] = splat2(py);
        zs[i] = splat2(pz);
        pm[i] = splat2(e2 * (px * px + py * py + pz * pz));
    }

    float acc[2][8][4];
#pragma unroll
    for (int t = 0; t < 2; t++)
#pragma unroll
        for (int k = 0; k < 8; k++)
#pragma unroll
            for (int j = 0; j < 4; j++) acc[t][k][j] = 0.0f;

    const float* xp = g_Xpk + ((size_t)s0 * 8 + (lane & 3)) * 8;
    const uint4* bf = reinterpret_cast<const uint4*>(g_Bfrag) + (size_t)s0 * 4 * 32 + lane;

#pragma unroll 2
    for (int s = 0; s < NSTEPS; s++) {
        // B fragments for this step (4 x LDG.128)
        uint4 bfr0 = __ldg(bf + 0 * 32);
        uint4 bfr1 = __ldg(bf + 1 * 32);
        uint4 bfr2 = __ldg(bf + 2 * 32);
        uint4 bfr3 = __ldg(bf + 3 * 32);
        bf += 4 * 32;

        // pair vectors: p=0 at +0, p=1 at +32 floats; (bx,by) then (bz,c)
        ulonglong2 A0 = *reinterpret_cast<const ulonglong2*>(xp);
        ulonglong2 B0 = *reinterpret_cast<const ulonglong2*>(xp + 4);
        ulonglong2 A1 = *reinterpret_cast<const ulonglong2*>(xp + 32);
        ulonglong2 B1 = *reinterpret_cast<const ulonglong2*>(xp + 36);
        xp += 64;

        // ---- mtile 0: phi -> fragments, then MMAs ----
        uint32_t ah0[4], ah1[4];
#pragma unroll
        for (int u = 0; u < 2; u++) {
            int ci = u;  // mtile 0
#pragma unroll
            for (int p = 0; p < 2; p++) {
                ull base = fadd2(p ? B1.y : B0.y, pm[ci]);
                ull tt = ffma2(xs[ci], p ? A1.x : A0.x,
                         ffma2(ys[ci], p ? A1.y : A0.y,
                         ffma2(zs[ci], p ? B1.x : B0.x, base)));
                float t0, t1; unpack2(tt, t0, t1);
                float sq0 = fast_sqrt(t0), sq1 = fast_sqrt(t1);
                uint32_t hb;
                asm("cvt.rn.f16x2.f32 %0, %1, %2;" : "=r"(hb) : "f"(sq1), "f"(sq0));
                ah0[u + 2 * p] = hb;
            }
        }
        mma_fp16(acc[0][0], ah0[0], ah0[1], ah0[2], ah0[3], bfr0.x, bfr0.y);
        mma_fp16(acc[0][1], ah0[0], ah0[1], ah0[2], ah0[3], bfr0.z, bfr0.w);
        mma_fp16(acc[0][2], ah0[0], ah0[1], ah0[2], ah0[3], bfr1.x, bfr1.y);
        mma_fp16(acc[0][3], ah0[0], ah0[1], ah0[2], ah0[3], bfr1.z, bfr1.w);
        mma_fp16(acc[0][4], ah0[0], ah0[1], ah0[2], ah0[3], bfr2.x, bfr2.y);
        mma_fp16(acc[0][5], ah0[0], ah0[1], ah0[2], ah0[3], bfr2.z, bfr2.w);
        mma_fp16(acc[0][6], ah0[0], ah0[1], ah0[2], ah0[3], bfr3.x, bfr3.y);
        mma_fp16(acc[0][7], ah0[0], ah0[1], ah0[2], ah0[3], bfr3.z, bfr3.w);

        // ---- mtile 1 ----
#pragma unroll
        for (int u = 0; u < 2; u++) {
            int ci = 2 + u;  // mtile 1
#pragma unroll
            for (int p = 0; p < 2; p++) {
                ull base = fadd2(p ? B1.y : B0.y, pm[ci]);
                ull tt = ffma2(xs[ci], p ? A1.x : A0.x,
                         ffma2(ys[ci], p ? A1.y : A0.y,
                         ffma2(zs[ci], p ? B1.x : B0.x, base)));
                float t0, t1; unpack2(tt, t0, t1);
                float sq0 = fast_sqrt(t0), sq1 = fast_sqrt(t1);
                uint32_t hb;
                asm("cvt.rn.f16x2.f32 %0, %1, %2;" : "=r"(hb) : "f"(sq1), "f"(sq0));
                ah1[u + 2 * p] = hb;
            }
        }
        mma_fp16(acc[1][0], ah1[0], ah1[1], ah1[2], ah1[3], bfr0.x, bfr0.y);
        mma_fp16(acc[1][1], ah1[0], ah1[1], ah1[2], ah1[3], bfr0.z, bfr0.w);
        mma_fp16(acc[1][2], ah1[0], ah1[1], ah1[2], ah1[3], bfr1.x, bfr1.y);
        mma_fp16(acc[1][3], ah1[0], ah1[1], ah1[2], ah1[3], bfr1.z, bfr1.w);
        mma_fp16(acc[1][4], ah1[0], ah1[1], ah1[2], ah1[3], bfr2.x, bfr2.y);
        mma_fp16(acc[1][5], ah1[0], ah1[1], ah1[2], ah1[3], bfr2.z, bfr2.w);
        mma_fp16(acc[1][6], ah1[0], ah1[1], ah1[2], ah1[3], bfr3.x, bfr3.y);
        mma_fp16(acc[1][7], ah1[0], ah1[1], ah1[2], ah1[3], bfr3.z, bfr3.w);
    }

    // epilogue: write partials
    float* part = g_part[ns];
#pragma unroll
    for (int mtile = 0; mtile < 2; mtile++) {
        int rbase = mwb + mtile * 16 + (lane >> 2);
#pragma unroll
        for (int kt = 0; kt < 8; kt++) {
            int c = kt * 8 + (lane & 3) * 2;
            *reinterpret_cast<float2*>(&part[(size_t)rbase * K_DIM + c]) =
                make_float2(acc[mtile][kt][0], acc[mtile][kt][1]);
            *reinterpret_cast<float2*>(&part[(size_t)(rbase + 8) * K_DIM + c]) =
                make_float2(acc[mtile][kt][2], acc[mtile][kt][3]);
        }
    }
}

// ---- reduce: 8 partials, one float4 per thread ----
__global__ __launch_bounds__(256)
void reduce_parts(float* __restrict__ out) {
    int i = blockIdx.x * 256 + threadIdx.x;
    float4 r = __ldg(reinterpret_cast<const float4*>(g_part[0]) + i);
#pragma unroll
    for (int p = 1; p < NSPLIT; p++) {
        float4 v = __ldg(reinterpret_cast<const float4*>(g_part[p]) + i);
        r.x += v.x; r.y += v.y; r.z += v.z; r.w += v.w;
    }
    reinterpret_cast<float4*>(out)[i] = r;
}

extern "C" void kernel_launch(void* const* d_in, const int* in_sizes, int n_in,
                              void* d_out, int out_size) {
    const float* Xp  = (const float*)d_in[0];
    const float* X   = (const float*)d_in[1];
    const float* W   = (const float*)d_in[2];
    const float* eps = (const float*)d_in[3];
    float* out = (float*)d_out;

    prep_all<<<BFRAG_U32 / 256, 256>>>(W, X, eps);

    dim3 grid(M_DIM / M_CTA, NSPLIT);   // 128 x 8 = 1024 CTAs
    rbf_fp16<<<grid, THREADS>>>(Xp, eps);

    reduce_parts<<<(M_DIM * K_DIM / 4) / 256, 256>>>(out);
}